// round 7
// baseline (speedup 1.0000x reference)
#include <cuda_runtime.h>
#include <cuda_bf16.h>
#include <stdint.h>

#define MAX_USERS 100000
#define EMBED 128
#define TILE_M 64            // rows per GEMM CTA (both paths)

// ---------------------------------------------------------------------------
// Scratch in __device__ globals (no allocation allowed anywhere)
// ---------------------------------------------------------------------------
__device__ float    g_xt[(size_t)MAX_USERS * EMBED];  // x @ W result
__device__ int      g_row_ptr[MAX_USERS + 1];
__device__ uint32_t g_wt32[2][EMBED * EMBED];         // [layer] W^T tf32 bits, [n][k]

// ---------------------------------------------------------------------------
// Tensor-path SMEM: A (64 x 132 f32) | W^T (128 x 132 tf32), padded stride 132
// floats -> conflict-free LDS.32 frag loads. FFMA path reuses the same buffer.
// ---------------------------------------------------------------------------
#define ROWF 132
#define ROWB (ROWF * 4)                  // 528
#define SM_A 0
#define SM_W (TILE_M * ROWB)             // 33792
#define SM_TOTAL (SM_W + EMBED * ROWB)   // 101376

// FFMA-path smem plan (within same dynamic buffer):
//   WsBuf[2][16][128] f32 (16384 B) then XsBuf[2][16][66] f32 (8448 B)
#define GKC 16
#define XS_PAD 66

__device__ __forceinline__ uint32_t cvt_tf32(float f) {
    uint32_t u;
    asm("cvt.rna.tf32.f32 %0, %1;" : "=r"(u) : "f"(f));
    return u;
}

#define MMA_TF32(c0, c1, c2, c3, a0, a1, a2, a3, b0, b1) \
    asm volatile("mma.sync.aligned.m16n8k8.row.col.f32.tf32.tf32.f32 " \
        "{%0,%1,%2,%3}, {%4,%5,%6,%7}, {%8,%9}, {%0,%1,%2,%3};" \
        : "+f"(c0), "+f"(c1), "+f"(c2), "+f"(c3) \
        : "r"(a0), "r"(a1), "r"(a2), "r"(a3), "r"(b0), "r"(b1))

// f32x2 packed-FMA helpers (SASS FFMA2 — only reachable via PTX)
typedef unsigned long long ull;
union F2U { float2 f2; ull u; };
#define FMA2(d, a, b) \
    asm("fma.rn.f32x2 %0, %1, %2, %0;" : "+l"(d) : "l"(a), "l"(b))
#define PACKDUP(u, f) \
    asm("mov.b64 %0, {%1, %1};" : "=l"(u) : "f"(f))
#define UNPACK2(lo, hi, u) \
    asm("mov.b64 {%0, %1}, %2;" : "=f"(lo), "=f"(hi) : "l"(u))

// ---------------------------------------------------------------------------
// Prep: W (row-major [k][n]) -> W^T tf32 bits in [n][k] order
// ---------------------------------------------------------------------------
__global__ void prep_w_kernel(const float* __restrict__ W0, const float* __restrict__ W1) {
    int layer = blockIdx.x >> 6;
    int idx = (blockIdx.x & 63) * 256 + threadIdx.x;
    const float* W = layer ? W1 : W0;
    int k = idx >> 7, n = idx & 127;
    g_wt32[layer][n * EMBED + k] = cvt_tf32(W[idx]);
}

// ---------------------------------------------------------------------------
// Build CSR row_ptr from sorted s_rows
// ---------------------------------------------------------------------------
__global__ void build_rowptr_kernel(const int* __restrict__ rows, int E, int M) {
    int e = blockIdx.x * blockDim.x + threadIdx.x;
    if (e >= E) return;
    int r = rows[e];
    if (e == 0) { for (int i = 0; i <= r; i++) g_row_ptr[i] = 0; }
    else { int rp = rows[e - 1]; for (int i = rp + 1; i <= r; i++) g_row_ptr[i] = e; }
    if (e == E - 1) { for (int i = r + 1; i <= M; i++) g_row_ptr[i] = E; }
}

// ---------------------------------------------------------------------------
// Hybrid GEMM: Xt = A[M,128] @ W[128,128].
//   CTA < nT         : tf32 mma.sync path (tensor pipe), rows [bid*64, +64)
//   CTA >= nT        : f32x2 FFMA path (fma pipe),       same row mapping
// The two populations co-reside on SMs and saturate disjoint pipes.
// ---------------------------------------------------------------------------
__global__ __launch_bounds__(256, 2) void gemm_hybrid_kernel(const float* __restrict__ A,
                                                             int layer,
                                                             const float* __restrict__ Wf,
                                                             float* __restrict__ Xt,
                                                             int M, int nT) {
    extern __shared__ char smem[];
    const int tid = threadIdx.x;
    const int row0 = blockIdx.x * TILE_M;

    if ((int)blockIdx.x < nT) {
        // ================= tf32 tensor path (R6, verified) =================
        const int wid = tid >> 5;
        const int lid = tid & 31;

        // Stage W^T tf32: thread -> (n = tid&127, half h = tid>>7)
        {
            int n = tid & 127, h = tid >> 7;
            const uint4* src = (const uint4*)(g_wt32[layer] + n * EMBED + h * 64);
            uint4* dst = (uint4*)(smem + SM_W + n * ROWB + h * 256);
#pragma unroll
            for (int c = 0; c < 16; c++) dst[c] = src[c];
        }
        // Stage A -> tf32: thread -> (r = tid&63, quarter q = tid>>6)
        {
            int r = tid & 63, q = tid >> 6;
            int grow = row0 + r;
            const float4* src = (grow < M) ? (const float4*)(A + (size_t)grow * EMBED + q * 32) : nullptr;
            uint4* dst = (uint4*)(smem + SM_A + r * ROWB + q * 128);
#pragma unroll
            for (int c = 0; c < 8; c++) {
                float4 f = src ? src[c] : make_float4(0.f, 0.f, 0.f, 0.f);
                dst[c] = make_uint4(cvt_tf32(f.x), cvt_tf32(f.y), cvt_tf32(f.z), cvt_tf32(f.w));
            }
        }
        __syncthreads();

        const int rg = wid >> 1;
        const int ch = wid & 1;
        const int g  = lid >> 2;
        const int tg = lid & 3;

        const char* Abase = smem + SM_A + (rg * 16 + g) * ROWB + tg * 4;
        const char* Bbase = smem + SM_W + (ch * 64 + g) * ROWB + tg * 4;

        float acc[8][4];
#pragma unroll
        for (int nb = 0; nb < 8; nb++)
#pragma unroll
            for (int i = 0; i < 4; i++) acc[nb][i] = 0.f;

#pragma unroll
        for (int ks = 0; ks < 16; ks++) {
            const int ko = ks * 32;
            uint32_t a0 = *(const uint32_t*)(Abase + ko);
            uint32_t a1 = *(const uint32_t*)(Abase + 8 * ROWB + ko);
            uint32_t a2 = *(const uint32_t*)(Abase + ko + 16);
            uint32_t a3 = *(const uint32_t*)(Abase + 8 * ROWB + ko + 16);
#pragma unroll
            for (int p = 0; p < 8; p++) {
                const char* Bp = Bbase + p * 8 * ROWB;
                uint32_t b0 = *(const uint32_t*)(Bp + ko);
                uint32_t b1 = *(const uint32_t*)(Bp + ko + 16);
                MMA_TF32(acc[p][0], acc[p][1], acc[p][2], acc[p][3], a0, a1, a2, a3, b0, b1);
            }
        }

        const int m0 = row0 + rg * 16 + g;
        const int m1 = m0 + 8;
#pragma unroll
        for (int nb = 0; nb < 8; nb++) {
            int col = ch * 64 + nb * 8 + tg * 2;
            if (m0 < M) *(float2*)(Xt + (size_t)m0 * EMBED + col) = make_float2(acc[nb][0], acc[nb][1]);
            if (m1 < M) *(float2*)(Xt + (size_t)m1 * EMBED + col) = make_float2(acc[nb][2], acc[nb][3]);
        }
    } else {
        // ================= f32x2 FFMA path (R2, verified) ==================
        float* WsBuf = (float*)smem;                    // [2][16][128]
        float* XsBuf = (float*)(smem + 2 * GKC * EMBED * 4); // [2][16][66]
#define WS(b, k, c) WsBuf[((b) * GKC + (k)) * EMBED + (c)]
#define XS(b, k, r) XsBuf[((b) * GKC + (k)) * XS_PAD + (r)]

        const int cx = tid & 31;
        const int ry = tid >> 5;

        const int w_kk0 = tid >> 5;
        const int w_c4  = tid & 31;
        const int a_r   = tid >> 2;
        const int a_k4  = tid & 3;

        ull acc[4][4];
#pragma unroll
        for (int p = 0; p < 4; p++)
#pragma unroll
            for (int c = 0; c < 4; c++) acc[p][c] = 0ull;

        float4 wreg0, wreg1, areg;
        {
            wreg0 = ((const float4*)(Wf + (size_t)(w_kk0) * EMBED))[w_c4];
            wreg1 = ((const float4*)(Wf + (size_t)(w_kk0 + 8) * EMBED))[w_c4];
            int grow = row0 + a_r;
            areg = make_float4(0.f, 0.f, 0.f, 0.f);
            if (grow < M) areg = ((const float4*)(A + (size_t)grow * EMBED))[a_k4];
        }
        {
            ((float4*)&WS(0, w_kk0, 0))[w_c4] = wreg0;
            ((float4*)&WS(0, w_kk0 + 8, 0))[w_c4] = wreg1;
            XS(0, a_k4 * 4 + 0, a_r) = areg.x;
            XS(0, a_k4 * 4 + 1, a_r) = areg.y;
            XS(0, a_k4 * 4 + 2, a_r) = areg.z;
            XS(0, a_k4 * 4 + 3, a_r) = areg.w;
        }
        __syncthreads();

        const int NCHUNK = EMBED / GKC;   // 8
#pragma unroll 1
        for (int c = 0; c < NCHUNK; c++) {
            const int buf = c & 1;
            if (c < NCHUNK - 1) {
                int kc = (c + 1) * GKC;
                wreg0 = ((const float4*)(Wf + (size_t)(kc + w_kk0) * EMBED))[w_c4];
                wreg1 = ((const float4*)(Wf + (size_t)(kc + w_kk0 + 8) * EMBED))[w_c4];
                int grow = row0 + a_r;
                areg = make_float4(0.f, 0.f, 0.f, 0.f);
                if (grow < M) areg = ((const float4*)(A + (size_t)grow * EMBED + kc))[a_k4];
            }

#pragma unroll
            for (int k = 0; k < GKC; k++) {
                float4 w = ((float4*)&WS(buf, k, 0))[cx];
                ull wp0, wp1, wp2, wp3;
                PACKDUP(wp0, w.x);
                PACKDUP(wp1, w.y);
                PACKDUP(wp2, w.z);
                PACKDUP(wp3, w.w);
#pragma unroll
                for (int p = 0; p < 4; p++) {
                    F2U a;
                    a.f2 = *(const float2*)&XS(buf, k, ry * 8 + 2 * p);
                    FMA2(acc[p][0], a.u, wp0);
                    FMA2(acc[p][1], a.u, wp1);
                    FMA2(acc[p][2], a.u, wp2);
                    FMA2(acc[p][3], a.u, wp3);
                }
            }

            if (c < NCHUNK - 1) {
                int nb = buf ^ 1;
                __syncthreads();
                ((float4*)&WS(nb, w_kk0, 0))[w_c4] = wreg0;
                ((float4*)&WS(nb, w_kk0 + 8, 0))[w_c4] = wreg1;
                XS(nb, a_k4 * 4 + 0, a_r) = areg.x;
                XS(nb, a_k4 * 4 + 1, a_r) = areg.y;
                XS(nb, a_k4 * 4 + 2, a_r) = areg.z;
                XS(nb, a_k4 * 4 + 3, a_r) = areg.w;
                __syncthreads();
            }
        }

#pragma unroll
        for (int p = 0; p < 4; p++) {
            float4 lo4, hi4;
            UNPACK2(lo4.x, hi4.x, acc[p][0]);
            UNPACK2(lo4.y, hi4.y, acc[p][1]);
            UNPACK2(lo4.z, hi4.z, acc[p][2]);
            UNPACK2(lo4.w, hi4.w, acc[p][3]);
            int rA = row0 + ry * 8 + 2 * p;
            int rB = rA + 1;
            if (rA < M) ((float4*)(Xt + (size_t)rA * EMBED))[cx] = lo4;
            if (rB < M) ((float4*)(Xt + (size_t)rB * EMBED))[cx] = hi4;
        }
#undef WS
#undef XS
    }
}

// ---------------------------------------------------------------------------
// SpMM + residual — R1 structure (at practical L2 cap). out0 fuses layer-0 copy.
// ---------------------------------------------------------------------------
__global__ __launch_bounds__(256) void spmm_kernel(const float* __restrict__ x,
                                                   const int* __restrict__ cols,
                                                   const float* __restrict__ vals,
                                                   float* __restrict__ out,
                                                   float* __restrict__ out0,
                                                   int M) {
    int warp = (blockIdx.x * blockDim.x + threadIdx.x) >> 5;
    int lane = threadIdx.x & 31;
    if (warp >= M) return;
    int r = warp;
    int s = g_row_ptr[r];
    int e = g_row_ptr[r + 1];

    float4 acc = make_float4(0.f, 0.f, 0.f, 0.f);
    for (int base = s; base < e; base += 32) {
        int idx = base + lane;
        int   c = 0;
        float v = 0.f;
        if (idx < e) { c = __ldg(cols + idx); v = __ldg(vals + idx); }
        int cnt = min(32, e - base);
        for (int j = 0; j < cnt; j++) {
            int   cj = __shfl_sync(0xffffffffu, c, j);
            float vj = __shfl_sync(0xffffffffu, v, j);
            float4 t4 = ((const float4*)(g_xt + (size_t)cj * EMBED))[lane];
            acc.x += vj * t4.x;
            acc.y += vj * t4.y;
            acc.z += vj * t4.z;
            acc.w += vj * t4.w;
        }
    }
    float4 xv = ((const float4*)(x + (size_t)r * EMBED))[lane];
    if (out0) ((float4*)(out0 + (size_t)r * EMBED))[lane] = xv;
    acc.x += xv.x; acc.y += xv.y; acc.z += xv.z; acc.w += xv.w;
    ((float4*)(out + (size_t)r * EMBED))[lane] = acc;
}

// ---------------------------------------------------------------------------
// kernel_launch
// ---------------------------------------------------------------------------
extern "C" void kernel_launch(void* const* d_in, const int* in_sizes, int n_in,
                              void* d_out, int out_size) {
    const float* ue   = (const float*)d_in[0];
    const int*   rows = (const int*)  d_in[1];
    const int*   cols = (const int*)  d_in[2];
    const float* vals = (const float*)d_in[3];
    const float* W0   = (const float*)d_in[4];
    const float* W1   = (const float*)d_in[5];
    float* out = (float*)d_out;

    const int M = in_sizes[0] / EMBED;
    const int E = in_sizes[1];
    const size_t layer_elems = (size_t)M * EMBED;

    float* xt_ptr;
    cudaGetSymbolAddress((void**)&xt_ptr, g_xt);

    cudaFuncSetAttribute(gemm_hybrid_kernel, cudaFuncAttributeMaxDynamicSharedMemorySize, SM_TOTAL);

    prep_w_kernel<<<128, 256>>>(W0, W1);
    build_rowptr_kernel<<<(E + 255) / 256, 256>>>(rows, E, M);

    const int gemm_blocks = (M + TILE_M - 1) / TILE_M;
    int nT = (int)(gemm_blocks * 0.53f);           // tensor-path share
    if (nT > gemm_blocks) nT = gemm_blocks;

    const int spmm_blocks = (M * 32 + 255) / 256;

    // Layer 1 (SpMM also emits out[0] = user_embeds)
    gemm_hybrid_kernel<<<gemm_blocks, 256, SM_TOTAL>>>(ue, 0, W0, xt_ptr, M, nT);
    spmm_kernel<<<spmm_blocks, 256>>>(ue, cols, vals, out + layer_elems, out, M);

    // Layer 2
    gemm_hybrid_kernel<<<gemm_blocks, 256, SM_TOTAL>>>(out + layer_elems, 1, W1, xt_ptr, M, nT);
    spmm_kernel<<<spmm_blocks, 256>>>(out + layer_elems, cols, vals,
                                      out + 2 * layer_elems, nullptr, M);
}

// round 8
// speedup vs baseline: 1.3086x; 1.3086x over previous
#include <cuda_runtime.h>
#include <cuda_bf16.h>
#include <stdint.h>

#define MAX_USERS 100000
#define EMBED 128
#define TILE_M 64            // rows per GEMM CTA

// ---------------------------------------------------------------------------
// Scratch in __device__ globals (no allocation allowed anywhere)
// ---------------------------------------------------------------------------
__device__ float    g_xt[(size_t)MAX_USERS * EMBED];  // x @ W result
__device__ int      g_row_ptr[MAX_USERS + 1];
__device__ uint16_t g_wt[2][EMBED * EMBED];           // [layer] W^T bf16, [n][k]

// ---------------------------------------------------------------------------
// SMEM: xh (64 x 256B) | wh (128 x 256B) = 48KB -> 4 CTAs/SM.
// Swizzle: addr = row*256 + (kb ^ ((row&7)<<4)) -> LDSM conflict-free,
// 16B staging stores stay aligned. (Layout verified in R5.)
// ---------------------------------------------------------------------------
#define SM_XH 0
#define SM_WH 16384
#define SM_TOTAL 49152

__device__ __forceinline__ uint32_t smem_u32(const void* p) {
    uint32_t a;
    asm("{ .reg .u64 t; cvta.to.shared.u64 t, %1; cvt.u32.u64 %0, t; }" : "=r"(a) : "l"(p));
    return a;
}

#define LDSM_X4(f0, f1, f2, f3, addr) \
    asm volatile("ldmatrix.sync.aligned.m8n8.x4.shared.b16 {%0,%1,%2,%3}, [%4];" \
        : "=r"(f0), "=r"(f1), "=r"(f2), "=r"(f3) : "r"(addr))

#define MMA_BF16(c0, c1, c2, c3, a0, a1, a2, a3, b0, b1) \
    asm volatile("mma.sync.aligned.m16n8k16.row.col.f32.bf16.bf16.f32 " \
        "{%0,%1,%2,%3}, {%4,%5,%6,%7}, {%8,%9}, {%0,%1,%2,%3};" \
        : "+f"(c0), "+f"(c1), "+f"(c2), "+f"(c3) \
        : "r"(a0), "r"(a1), "r"(a2), "r"(a3), "r"(b0), "r"(b1))

// ---------------------------------------------------------------------------
// Prep: W (row-major [k][n]) -> W^T bf16 in [n][k] order
// ---------------------------------------------------------------------------
__global__ void prep_w_kernel(const float* __restrict__ W0, const float* __restrict__ W1) {
    int layer = blockIdx.x >> 6;
    int idx = (blockIdx.x & 63) * 256 + threadIdx.x;   // 0..16383
    const float* W = layer ? W1 : W0;
    int k = idx >> 7, n = idx & 127;
    __nv_bfloat16 h = __float2bfloat16(W[idx]);
    g_wt[layer][n * EMBED + k] = *(uint16_t*)&h;
}

// ---------------------------------------------------------------------------
// Build CSR row_ptr from sorted s_rows
// ---------------------------------------------------------------------------
__global__ void build_rowptr_kernel(const int* __restrict__ rows, int E, int M) {
    int e = blockIdx.x * blockDim.x + threadIdx.x;
    if (e >= E) return;
    int r = rows[e];
    if (e == 0) { for (int i = 0; i <= r; i++) g_row_ptr[i] = 0; }
    else { int rp = rows[e - 1]; for (int i = rp + 1; i <= r; i++) g_row_ptr[i] = e; }
    if (e == E - 1) { for (int i = r + 1; i <= M; i++) g_row_ptr[i] = E; }
}

// ---------------------------------------------------------------------------
// bf16 single-product HMMA GEMM: Xt = A[M,128] @ W[128,128].
// CTA: 256 threads / 8 warps; warp (rg = wid>>1, ch = wid&1):
//   rows rg*16..+15, cols ch*64..+63.
// ---------------------------------------------------------------------------
__global__ __launch_bounds__(256, 4) void gemm_bf16_kernel(const float* __restrict__ A,
                                                           int layer,
                                                           float* __restrict__ Xt,
                                                           int M) {
    extern __shared__ char smem[];
    const uint32_t sb = smem_u32(smem);
    const int tid = threadIdx.x;
    const int wid = tid >> 5;
    const int lid = tid & 31;
    const int row0 = blockIdx.x * TILE_M;

    // ---- Stage W^T bf16 (swizzled): thread t -> n = t>>1, 128B half h = t&1
    {
        const uint4* gh = (const uint4*)g_wt[layer];
        int n = tid >> 1, h = tid & 1;
        uint32_t nsw = (uint32_t)((n & 7) << 4);
        uint32_t rbase = (uint32_t)(n * 256);
#pragma unroll
        for (int c = 0; c < 8; c++) {
            uint32_t kb = (uint32_t)(h * 128 + c * 16);
            *(uint4*)(smem + SM_WH + rbase + (kb ^ nsw)) = gh[n * 16 + h * 8 + c];
        }
    }

    // ---- Stage A rows -> bf16 (swizzled): thread t -> row t>>2, quarter t&3
    {
        int r = tid >> 2, q = tid & 3;           // quarter = 32 k-elements
        int grow = row0 + r;
        const float4* src = (grow < M) ? (const float4*)(A + (size_t)grow * EMBED + q * 32) : nullptr;
        uint32_t rsw = (uint32_t)((r & 7) << 4);
        uint32_t rbase = (uint32_t)(r * 256);
#pragma unroll
        for (int c = 0; c < 4; c++) {            // 4 x 16B chunks (8 bf16 each)
            uint32_t hp[4];
#pragma unroll
            for (int i = 0; i < 2; i++) {
                float4 f = src ? src[c * 2 + i] : make_float4(0.f, 0.f, 0.f, 0.f);
                __nv_bfloat16 h0 = __float2bfloat16(f.x), h1 = __float2bfloat16(f.y);
                __nv_bfloat16 h2 = __float2bfloat16(f.z), h3 = __float2bfloat16(f.w);
                hp[2 * i]     = (uint32_t)*(uint16_t*)&h0 | ((uint32_t)*(uint16_t*)&h1 << 16);
                hp[2 * i + 1] = (uint32_t)*(uint16_t*)&h2 | ((uint32_t)*(uint16_t*)&h3 << 16);
            }
            uint32_t kb = (uint32_t)(q * 64 + c * 16);
            *(uint4*)(smem + SM_XH + rbase + (kb ^ rsw)) = make_uint4(hp[0], hp[1], hp[2], hp[3]);
        }
    }
    __syncthreads();

    // ---- Fragment addressing (identical mapping to R5, verified)
    const int rg = wid >> 1;                // row group: rows rg*16..+15
    const int ch = wid & 1;                 // col half: cols ch*64..+63
    const uint32_t lsw = (uint32_t)((lid & 7) << 4);

    const int a_m = (((lid >> 3) & 1) << 3) + (lid & 7);
    const uint32_t a_kb0 = (uint32_t)((((lid >> 4) & 1) << 3) * 2);
    const uint32_t a_rbase = (uint32_t)((rg * 16 + a_m) * 256);

    const int b_nl = (((lid >> 4) & 1) << 3) + (lid & 7);
    const uint32_t b_kb0 = (uint32_t)((((lid >> 3) & 1) << 3) * 2);
    const uint32_t b_rbase0 = (uint32_t)((ch * 64 + b_nl) * 256);

    float acc[8][4];
#pragma unroll
    for (int nb = 0; nb < 8; nb++)
#pragma unroll
        for (int i = 0; i < 4; i++) acc[nb][i] = 0.f;

#pragma unroll
    for (int ks = 0; ks < 8; ks++) {
        const uint32_t akb = (a_kb0 + (uint32_t)(ks * 32)) ^ lsw;
        const uint32_t bkb = (b_kb0 + (uint32_t)(ks * 32)) ^ lsw;
        uint32_t a0, a1, a2, a3;
        LDSM_X4(a0, a1, a2, a3, sb + SM_XH + a_rbase + akb);
#pragma unroll
        for (int p = 0; p < 4; p++) {
            const uint32_t brow = b_rbase0 + (uint32_t)(p * 16 * 256);
            uint32_t b0, b1, b2, b3;
            LDSM_X4(b0, b1, b2, b3, sb + SM_WH + brow + bkb);
            MMA_BF16(acc[2 * p][0], acc[2 * p][1], acc[2 * p][2], acc[2 * p][3],
                     a0, a1, a2, a3, b0, b1);
            MMA_BF16(acc[2 * p + 1][0], acc[2 * p + 1][1], acc[2 * p + 1][2], acc[2 * p + 1][3],
                     a0, a1, a2, a3, b2, b3);
        }
    }

    // ---- Epilogue: (c0,c1)=row g cols 2q..2q+1 ; (c2,c3)=row g+8
    const int g = lid >> 2;
    const int q = lid & 3;
    const int m0 = row0 + rg * 16 + g;
    const int m1 = m0 + 8;
#pragma unroll
    for (int nb = 0; nb < 8; nb++) {
        int col = ch * 64 + nb * 8 + q * 2;
        if (m0 < M) *(float2*)(Xt + (size_t)m0 * EMBED + col) = make_float2(acc[nb][0], acc[nb][1]);
        if (m1 < M) *(float2*)(Xt + (size_t)m1 * EMBED + col) = make_float2(acc[nb][2], acc[nb][3]);
    }
}

// ---------------------------------------------------------------------------
// SpMM + residual — R1 structure (at practical LTS cap). out0 fuses layer-0 copy.
// ---------------------------------------------------------------------------
__global__ __launch_bounds__(256) void spmm_kernel(const float* __restrict__ x,
                                                   const int* __restrict__ cols,
                                                   const float* __restrict__ vals,
                                                   float* __restrict__ out,
                                                   float* __restrict__ out0,
                                                   int M) {
    int warp = (blockIdx.x * blockDim.x + threadIdx.x) >> 5;
    int lane = threadIdx.x & 31;
    if (warp >= M) return;
    int r = warp;
    int s = g_row_ptr[r];
    int e = g_row_ptr[r + 1];

    float4 acc = make_float4(0.f, 0.f, 0.f, 0.f);
    for (int base = s; base < e; base += 32) {
        int idx = base + lane;
        int   c = 0;
        float v = 0.f;
        if (idx < e) { c = __ldg(cols + idx); v = __ldg(vals + idx); }
        int cnt = min(32, e - base);
        for (int j = 0; j < cnt; j++) {
            int   cj = __shfl_sync(0xffffffffu, c, j);
            float vj = __shfl_sync(0xffffffffu, v, j);
            float4 t4 = ((const float4*)(g_xt + (size_t)cj * EMBED))[lane];
            acc.x += vj * t4.x;
            acc.y += vj * t4.y;
            acc.z += vj * t4.z;
            acc.w += vj * t4.w;
        }
    }
    float4 xv = ((const float4*)(x + (size_t)r * EMBED))[lane];
    if (out0) ((float4*)(out0 + (size_t)r * EMBED))[lane] = xv;
    acc.x += xv.x; acc.y += xv.y; acc.z += xv.z; acc.w += xv.w;
    ((float4*)(out + (size_t)r * EMBED))[lane] = acc;
}

// ---------------------------------------------------------------------------
// kernel_launch
// ---------------------------------------------------------------------------
extern "C" void kernel_launch(void* const* d_in, const int* in_sizes, int n_in,
                              void* d_out, int out_size) {
    const float* ue   = (const float*)d_in[0];
    const int*   rows = (const int*)  d_in[1];
    const int*   cols = (const int*)  d_in[2];
    const float* vals = (const float*)d_in[3];
    const float* W0   = (const float*)d_in[4];
    const float* W1   = (const float*)d_in[5];
    float* out = (float*)d_out;

    const int M = in_sizes[0] / EMBED;
    const int E = in_sizes[1];
    const size_t layer_elems = (size_t)M * EMBED;

    float* xt_ptr;
    cudaGetSymbolAddress((void**)&xt_ptr, g_xt);

    cudaFuncSetAttribute(gemm_bf16_kernel, cudaFuncAttributeMaxDynamicSharedMemorySize, SM_TOTAL);

    prep_w_kernel<<<128, 256>>>(W0, W1);
    build_rowptr_kernel<<<(E + 255) / 256, 256>>>(rows, E, M);

    const int gemm_blocks = (M + TILE_M - 1) / TILE_M;
    const int spmm_blocks = (M * 32 + 255) / 256;

    // Layer 1 (SpMM also emits out[0] = user_embeds)
    gemm_bf16_kernel<<<gemm_blocks, 256, SM_TOTAL>>>(ue, 0, xt_ptr, M);
    spmm_kernel<<<spmm_blocks, 256>>>(ue, cols, vals, out + layer_elems, out, M);

    // Layer 2
    gemm_bf16_kernel<<<gemm_blocks, 256, SM_TOTAL>>>(out + layer_elems, 1, xt_ptr, M);
    spmm_kernel<<<spmm_blocks, 256>>>(out + layer_elems, cols, vals,
                                      out + 2 * layer_elems, nullptr, M);
}

// round 9
// speedup vs baseline: 1.4543x; 1.1113x over previous
#include <cuda_runtime.h>
#include <cuda_bf16.h>
#include <stdint.h>

#define MAX_USERS 100000
#define EMBED 128
#define TILE_M 64            // rows per GEMM CTA

// ---------------------------------------------------------------------------
// Scratch in __device__ globals (no allocation allowed anywhere)
// ---------------------------------------------------------------------------
__device__ uint16_t g_xtb[(size_t)MAX_USERS * EMBED]; // x @ W result, bf16
__device__ int      g_row_ptr[MAX_USERS + 1];
__device__ uint16_t g_wt[2][EMBED * EMBED];           // [layer] W^T bf16, [n][k]

// ---------------------------------------------------------------------------
// SMEM: xh (64x256B) | xl (64x256B) | w (128x256B) = 64KB -> 3 CTAs/SM.
// Swizzle: addr = row*256 + (kb ^ ((row&7)<<4)) (layout verified R5/R8).
// ---------------------------------------------------------------------------
#define SM_XH 0
#define SM_XL 16384
#define SM_WH 32768
#define SM_TOTAL 65536

__device__ __forceinline__ uint32_t smem_u32(const void* p) {
    uint32_t a;
    asm("{ .reg .u64 t; cvta.to.shared.u64 t, %1; cvt.u32.u64 %0, t; }" : "=r"(a) : "l"(p));
    return a;
}

#define LDSM_X4(f0, f1, f2, f3, addr) \
    asm volatile("ldmatrix.sync.aligned.m8n8.x4.shared.b16 {%0,%1,%2,%3}, [%4];" \
        : "=r"(f0), "=r"(f1), "=r"(f2), "=r"(f3) : "r"(addr))

#define MMA_BF16(c0, c1, c2, c3, a0, a1, a2, a3, b0, b1) \
    asm volatile("mma.sync.aligned.m16n8k16.row.col.f32.bf16.bf16.f32 " \
        "{%0,%1,%2,%3}, {%4,%5,%6,%7}, {%8,%9}, {%0,%1,%2,%3};" \
        : "+f"(c0), "+f"(c1), "+f"(c2), "+f"(c3) \
        : "r"(a0), "r"(a1), "r"(a2), "r"(a3), "r"(b0), "r"(b1))

// ---------------------------------------------------------------------------
// Prep: W (row-major [k][n]) -> W^T bf16 in [n][k] order
// ---------------------------------------------------------------------------
__global__ void prep_w_kernel(const float* __restrict__ W0, const float* __restrict__ W1) {
    int layer = blockIdx.x >> 6;
    int idx = (blockIdx.x & 63) * 256 + threadIdx.x;   // 0..16383
    const float* W = layer ? W1 : W0;
    int k = idx >> 7, n = idx & 127;
    __nv_bfloat16 h = __float2bfloat16(W[idx]);
    g_wt[layer][n * EMBED + k] = *(uint16_t*)&h;
}

// ---------------------------------------------------------------------------
// Build CSR row_ptr from sorted s_rows
// ---------------------------------------------------------------------------
__global__ void build_rowptr_kernel(const int* __restrict__ rows, int E, int M) {
    int e = blockIdx.x * blockDim.x + threadIdx.x;
    if (e >= E) return;
    int r = rows[e];
    if (e == 0) { for (int i = 0; i <= r; i++) g_row_ptr[i] = 0; }
    else { int rp = rows[e - 1]; for (int i = rp + 1; i <= r; i++) g_row_ptr[i] = e; }
    if (e == E - 1) { for (int i = r + 1; i <= M; i++) g_row_ptr[i] = E; }
}

// ---------------------------------------------------------------------------
// 2-product bf16 HMMA GEMM: Xt(bf16) = A[M,128] @ W[128,128]
//   x@W = xh@W + xl@W  (A split exactly; only W carries rounding error)
// CTA: 256 threads / 8 warps; warp (rg = wid>>1, ch = wid&1).
// ---------------------------------------------------------------------------
__global__ __launch_bounds__(256, 3) void gemm_2p_kernel(const float* __restrict__ A,
                                                         int layer,
                                                         uint16_t* __restrict__ Xtb,
                                                         int M) {
    extern __shared__ char smem[];
    const uint32_t sb = smem_u32(smem);
    const int tid = threadIdx.x;
    const int wid = tid >> 5;
    const int lid = tid & 31;
    const int row0 = blockIdx.x * TILE_M;

    // ---- Stage W^T bf16 (swizzled): thread t -> n = t>>1, 128B half h = t&1
    {
        const uint4* gh = (const uint4*)g_wt[layer];
        int n = tid >> 1, h = tid & 1;
        uint32_t nsw = (uint32_t)((n & 7) << 4);
        uint32_t rbase = (uint32_t)(n * 256);
#pragma unroll
        for (int c = 0; c < 8; c++) {
            uint32_t kb = (uint32_t)(h * 128 + c * 16);
            *(uint4*)(smem + SM_WH + rbase + (kb ^ nsw)) = gh[n * 16 + h * 8 + c];
        }
    }

    // ---- Stage A rows -> bf16 hi/lo (swizzled): thread t -> row t>>2, quarter t&3
    {
        int r = tid >> 2, q = tid & 3;           // quarter = 32 k-elements
        int grow = row0 + r;
        const float4* src = (grow < M) ? (const float4*)(A + (size_t)grow * EMBED + q * 32) : nullptr;
        uint32_t rsw = (uint32_t)((r & 7) << 4);
        uint32_t rbase = (uint32_t)(r * 256);
#pragma unroll
        for (int c = 0; c < 4; c++) {            // 4 x 16B chunks (8 bf16 each)
            uint32_t hp[4], lp[4];
#pragma unroll
            for (int i = 0; i < 2; i++) {
                float4 f = src ? src[c * 2 + i] : make_float4(0.f, 0.f, 0.f, 0.f);
                __nv_bfloat16 h0 = __float2bfloat16(f.x), h1 = __float2bfloat16(f.y);
                __nv_bfloat16 h2 = __float2bfloat16(f.z), h3 = __float2bfloat16(f.w);
                __nv_bfloat16 l0 = __float2bfloat16(f.x - __bfloat162float(h0));
                __nv_bfloat16 l1 = __float2bfloat16(f.y - __bfloat162float(h1));
                __nv_bfloat16 l2 = __float2bfloat16(f.z - __bfloat162float(h2));
                __nv_bfloat16 l3 = __float2bfloat16(f.w - __bfloat162float(h3));
                hp[2 * i]     = (uint32_t)*(uint16_t*)&h0 | ((uint32_t)*(uint16_t*)&h1 << 16);
                hp[2 * i + 1] = (uint32_t)*(uint16_t*)&h2 | ((uint32_t)*(uint16_t*)&h3 << 16);
                lp[2 * i]     = (uint32_t)*(uint16_t*)&l0 | ((uint32_t)*(uint16_t*)&l1 << 16);
                lp[2 * i + 1] = (uint32_t)*(uint16_t*)&l2 | ((uint32_t)*(uint16_t*)&l3 << 16);
            }
            uint32_t kb = (uint32_t)(q * 64 + c * 16);
            *(uint4*)(smem + SM_XH + rbase + (kb ^ rsw)) = make_uint4(hp[0], hp[1], hp[2], hp[3]);
            *(uint4*)(smem + SM_XL + rbase + (kb ^ rsw)) = make_uint4(lp[0], lp[1], lp[2], lp[3]);
        }
    }
    __syncthreads();

    // ---- Fragment addressing (verified mapping, R5/R8)
    const int rg = wid >> 1;
    const int ch = wid & 1;
    const uint32_t lsw = (uint32_t)((lid & 7) << 4);

    const int a_m = (((lid >> 3) & 1) << 3) + (lid & 7);
    const uint32_t a_kb0 = (uint32_t)((((lid >> 4) & 1) << 3) * 2);
    const uint32_t a_rbase = (uint32_t)((rg * 16 + a_m) * 256);

    const int b_nl = (((lid >> 4) & 1) << 3) + (lid & 7);
    const uint32_t b_kb0 = (uint32_t)((((lid >> 3) & 1) << 3) * 2);
    const uint32_t b_rbase0 = (uint32_t)((ch * 64 + b_nl) * 256);

    float acc[8][4];
#pragma unroll
    for (int nb = 0; nb < 8; nb++)
#pragma unroll
        for (int i = 0; i < 4; i++) acc[nb][i] = 0.f;

#pragma unroll
    for (int ks = 0; ks < 8; ks++) {
        const uint32_t akb = (a_kb0 + (uint32_t)(ks * 32)) ^ lsw;
        const uint32_t bkb = (b_kb0 + (uint32_t)(ks * 32)) ^ lsw;
        uint32_t ah0, ah1, ah2, ah3, al0, al1, al2, al3;
        LDSM_X4(ah0, ah1, ah2, ah3, sb + SM_XH + a_rbase + akb);
        LDSM_X4(al0, al1, al2, al3, sb + SM_XL + a_rbase + akb);
#pragma unroll
        for (int p = 0; p < 4; p++) {
            const uint32_t brow = b_rbase0 + (uint32_t)(p * 16 * 256);
            uint32_t b0, b1, b2, b3;
            LDSM_X4(b0, b1, b2, b3, sb + SM_WH + brow + bkb);
            float* c0 = acc[2 * p];
            float* c1 = acc[2 * p + 1];
            MMA_BF16(c0[0], c0[1], c0[2], c0[3], ah0, ah1, ah2, ah3, b0, b1);
            MMA_BF16(c1[0], c1[1], c1[2], c1[3], ah0, ah1, ah2, ah3, b2, b3);
            MMA_BF16(c0[0], c0[1], c0[2], c0[3], al0, al1, al2, al3, b0, b1);
            MMA_BF16(c1[0], c1[1], c1[2], c1[3], al0, al1, al2, al3, b2, b3);
        }
    }

    // ---- Epilogue: write bf16 xt. (c0,c1)=row g cols 2q..+1 ; (c2,c3)=row g+8
    const int g = lid >> 2;
    const int q = lid & 3;
    const int m0 = row0 + rg * 16 + g;
    const int m1 = m0 + 8;
#pragma unroll
    for (int nb = 0; nb < 8; nb++) {
        int col = ch * 64 + nb * 8 + q * 2;
        __nv_bfloat16 p00 = __float2bfloat16(acc[nb][0]);
        __nv_bfloat16 p01 = __float2bfloat16(acc[nb][1]);
        __nv_bfloat16 p10 = __float2bfloat16(acc[nb][2]);
        __nv_bfloat16 p11 = __float2bfloat16(acc[nb][3]);
        uint32_t w0 = (uint32_t)*(uint16_t*)&p00 | ((uint32_t)*(uint16_t*)&p01 << 16);
        uint32_t w1 = (uint32_t)*(uint16_t*)&p10 | ((uint32_t)*(uint16_t*)&p11 << 16);
        if (m0 < M) *(uint32_t*)(Xtb + (size_t)m0 * EMBED + col) = w0;
        if (m1 < M) *(uint32_t*)(Xtb + (size_t)m1 * EMBED + col) = w1;
    }
}

// ---------------------------------------------------------------------------
// SpMM + residual, bf16 gather: out[r] = x[r] + sum vals[e] * bf16(xt)[cols[e]]
// One warp per row; lane owns 4 cols (uint2 = 4 bf16 = 8 B gather per lane).
// ---------------------------------------------------------------------------
__global__ __launch_bounds__(256) void spmm_kernel(const float* __restrict__ x,
                                                   const int* __restrict__ cols,
                                                   const float* __restrict__ vals,
                                                   float* __restrict__ out,
                                                   float* __restrict__ out0,
                                                   int M) {
    int warp = (blockIdx.x * blockDim.x + threadIdx.x) >> 5;
    int lane = threadIdx.x & 31;
    if (warp >= M) return;
    int r = warp;
    int s = g_row_ptr[r];
    int e = g_row_ptr[r + 1];

    float4 acc = make_float4(0.f, 0.f, 0.f, 0.f);
    for (int base = s; base < e; base += 32) {
        int idx = base + lane;
        int   c = 0;
        float v = 0.f;
        if (idx < e) { c = __ldg(cols + idx); v = __ldg(vals + idx); }
        int cnt = min(32, e - base);
        for (int j = 0; j < cnt; j++) {
            int   cj = __shfl_sync(0xffffffffu, c, j);
            float vj = __shfl_sync(0xffffffffu, v, j);
            uint2 raw = ((const uint2*)(g_xtb + (size_t)cj * EMBED))[lane];
            float f0 = __uint_as_float(raw.x << 16);
            float f1 = __uint_as_float(raw.x & 0xffff0000u);
            float f2 = __uint_as_float(raw.y << 16);
            float f3 = __uint_as_float(raw.y & 0xffff0000u);
            acc.x += vj * f0;
            acc.y += vj * f1;
            acc.z += vj * f2;
            acc.w += vj * f3;
        }
    }
    float4 xv = ((const float4*)(x + (size_t)r * EMBED))[lane];
    if (out0) ((float4*)(out0 + (size_t)r * EMBED))[lane] = xv;
    acc.x += xv.x; acc.y += xv.y; acc.z += xv.z; acc.w += xv.w;
    ((float4*)(out + (size_t)r * EMBED))[lane] = acc;
}

// ---------------------------------------------------------------------------
// kernel_launch
// ---------------------------------------------------------------------------
extern "C" void kernel_launch(void* const* d_in, const int* in_sizes, int n_in,
                              void* d_out, int out_size) {
    const float* ue   = (const float*)d_in[0];
    const int*   rows = (const int*)  d_in[1];
    const int*   cols = (const int*)  d_in[2];
    const float* vals = (const float*)d_in[3];
    const float* W0   = (const float*)d_in[4];
    const float* W1   = (const float*)d_in[5];
    float* out = (float*)d_out;

    const int M = in_sizes[0] / EMBED;
    const int E = in_sizes[1];
    const size_t layer_elems = (size_t)M * EMBED;

    uint16_t* xtb_ptr;
    cudaGetSymbolAddress((void**)&xtb_ptr, g_xtb);

    cudaFuncSetAttribute(gemm_2p_kernel, cudaFuncAttributeMaxDynamicSharedMemorySize, SM_TOTAL);

    prep_w_kernel<<<128, 256>>>(W0, W1);
    build_rowptr_kernel<<<(E + 255) / 256, 256>>>(rows, E, M);

    const int gemm_blocks = (M + TILE_M - 1) / TILE_M;
    const int spmm_blocks = (M * 32 + 255) / 256;

    // Layer 1 (SpMM also emits out[0] = user_embeds)
    gemm_2p_kernel<<<gemm_blocks, 256, SM_TOTAL>>>(ue, 0, xtb_ptr, M);
    spmm_kernel<<<spmm_blocks, 256>>>(ue, cols, vals, out + layer_elems, out, M);

    // Layer 2
    gemm_2p_kernel<<<gemm_blocks, 256, SM_TOTAL>>>(out + layer_elems, 1, xtb_ptr, M);
    spmm_kernel<<<spmm_blocks, 256>>>(out + layer_elems, cols, vals,
                                      out + 2 * layer_elems, nullptr, M);
}

// round 10
// speedup vs baseline: 1.4817x; 1.0188x over previous
#include <cuda_runtime.h>
#include <cuda_bf16.h>
#include <stdint.h>

#define MAX_USERS 100000
#define EMBED 128
#define TILE_M 128           // rows per GEMM CTA

// ---------------------------------------------------------------------------
// Scratch in __device__ globals (no allocation allowed anywhere)
// ---------------------------------------------------------------------------
__device__ uint16_t g_xtb[(size_t)MAX_USERS * EMBED]; // x @ W result, bf16
__device__ int      g_row_ptr[MAX_USERS + 1];
__device__ uint16_t g_wt[2][EMBED * EMBED];           // [layer] W^T bf16, [n][k]

// ---------------------------------------------------------------------------
// SMEM: xh (128x256B) | xl (128x256B) | w (128x256B) = 96KB -> 2 CTAs/SM.
// Swizzle: addr = row*256 + (kb ^ ((row&7)<<4)) (layout verified R5/R8/R9).
// ---------------------------------------------------------------------------
#define SM_XH 0
#define SM_XL 32768
#define SM_WH 65536
#define SM_TOTAL 98304

__device__ __forceinline__ uint32_t smem_u32(const void* p) {
    uint32_t a;
    asm("{ .reg .u64 t; cvta.to.shared.u64 t, %1; cvt.u32.u64 %0, t; }" : "=r"(a) : "l"(p));
    return a;
}

#define LDSM_X4(f0, f1, f2, f3, addr) \
    asm volatile("ldmatrix.sync.aligned.m8n8.x4.shared.b16 {%0,%1,%2,%3}, [%4];" \
        : "=r"(f0), "=r"(f1), "=r"(f2), "=r"(f3) : "r"(addr))

#define MMA_BF16(c0, c1, c2, c3, a0, a1, a2, a3, b0, b1) \
    asm volatile("mma.sync.aligned.m16n8k16.row.col.f32.bf16.bf16.f32 " \
        "{%0,%1,%2,%3}, {%4,%5,%6,%7}, {%8,%9}, {%0,%1,%2,%3};" \
        : "+f"(c0), "+f"(c1), "+f"(c2), "+f"(c3) \
        : "r"(a0), "r"(a1), "r"(a2), "r"(a3), "r"(b0), "r"(b1))

__device__ __forceinline__ float bf_lo(uint32_t u) { return __uint_as_float(u << 16); }
__device__ __forceinline__ float bf_hi(uint32_t u) { return __uint_as_float(u & 0xffff0000u); }

// ---------------------------------------------------------------------------
// Prep: W (row-major [k][n]) -> W^T bf16 in [n][k] order
// ---------------------------------------------------------------------------
__global__ void prep_w_kernel(const float* __restrict__ W0, const float* __restrict__ W1) {
    int layer = blockIdx.x >> 6;
    int idx = (blockIdx.x & 63) * 256 + threadIdx.x;   // 0..16383
    const float* W = layer ? W1 : W0;
    int k = idx >> 7, n = idx & 127;
    __nv_bfloat16 h = __float2bfloat16(W[idx]);
    g_wt[layer][n * EMBED + k] = *(uint16_t*)&h;
}

// ---------------------------------------------------------------------------
// Build CSR row_ptr from sorted s_rows
// ---------------------------------------------------------------------------
__global__ void build_rowptr_kernel(const int* __restrict__ rows, int E, int M) {
    int e = blockIdx.x * blockDim.x + threadIdx.x;
    if (e >= E) return;
    int r = rows[e];
    if (e == 0) { for (int i = 0; i <= r; i++) g_row_ptr[i] = 0; }
    else { int rp = rows[e - 1]; for (int i = rp + 1; i <= r; i++) g_row_ptr[i] = e; }
    if (e == E - 1) { for (int i = r + 1; i <= M; i++) g_row_ptr[i] = E; }
}

// ---------------------------------------------------------------------------
// 2-product bf16 HMMA GEMM: Xt(bf16) = A[M,128] @ W[128,128]
//   x@W = xh@W + xl@W  (A split exactly; only W carries rounding error)
// CTA: 256 threads / 8 warps; TILE_M=128; warp w: rows w*16..+15, all 128 cols.
// ---------------------------------------------------------------------------
__global__ __launch_bounds__(256, 2) void gemm_2p_kernel(const float* __restrict__ A,
                                                         int layer,
                                                         uint16_t* __restrict__ Xtb,
                                                         int M) {
    extern __shared__ char smem[];
    const uint32_t sb = smem_u32(smem);
    const int tid = threadIdx.x;
    const int wid = tid >> 5;
    const int lid = tid & 31;
    const int row0 = blockIdx.x * TILE_M;

    // ---- Stage W^T bf16 (swizzled): thread t -> n = t>>1, 128B half h = t&1
    {
        const uint4* gh = (const uint4*)g_wt[layer];
        int n = tid >> 1, h = tid & 1;
        uint32_t nsw = (uint32_t)((n & 7) << 4);
        uint32_t rbase = (uint32_t)(n * 256);
#pragma unroll
        for (int c = 0; c < 8; c++) {
            uint32_t kb = (uint32_t)(h * 128 + c * 16);
            *(uint4*)(smem + SM_WH + rbase + (kb ^ nsw)) = gh[n * 16 + h * 8 + c];
        }
    }

    // ---- Stage A rows -> bf16 hi/lo (swizzled): thread t -> row t&127, half t>>7
    // Rows beyond M are clamped to M-1 (their outputs are never read or written).
    {
        int r = tid & 127, h = tid >> 7;
        int grow = row0 + r;
        if (grow >= M) grow = M - 1;
        const float4* src = (const float4*)(A + (size_t)grow * EMBED + h * 64);
        uint32_t rsw = (uint32_t)((r & 7) << 4);
        uint32_t rbase = (uint32_t)(r * 256);
#pragma unroll
        for (int c = 0; c < 8; c++) {            // 8 x 16B chunks (8 bf16 each)
            uint32_t hp[4], lp[4];
#pragma unroll
            for (int i = 0; i < 2; i++) {
                float4 f = src[c * 2 + i];
                __nv_bfloat16 h0 = __float2bfloat16(f.x), h1 = __float2bfloat16(f.y);
                __nv_bfloat16 h2 = __float2bfloat16(f.z), h3 = __float2bfloat16(f.w);
                __nv_bfloat16 l0 = __float2bfloat16(f.x - __bfloat162float(h0));
                __nv_bfloat16 l1 = __float2bfloat16(f.y - __bfloat162float(h1));
                __nv_bfloat16 l2 = __float2bfloat16(f.z - __bfloat162float(h2));
                __nv_bfloat16 l3 = __float2bfloat16(f.w - __bfloat162float(h3));
                hp[2 * i]     = (uint32_t)*(uint16_t*)&h0 | ((uint32_t)*(uint16_t*)&h1 << 16);
                hp[2 * i + 1] = (uint32_t)*(uint16_t*)&h2 | ((uint32_t)*(uint16_t*)&h3 << 16);
                lp[2 * i]     = (uint32_t)*(uint16_t*)&l0 | ((uint32_t)*(uint16_t*)&l1 << 16);
                lp[2 * i + 1] = (uint32_t)*(uint16_t*)&l2 | ((uint32_t)*(uint16_t*)&l3 << 16);
            }
            uint32_t kb = (uint32_t)(h * 128 + c * 16);
            uint32_t off = rbase + (kb ^ rsw);
            *(uint4*)(smem + SM_XH + off) = make_uint4(hp[0], hp[1], hp[2], hp[3]);
            *(uint4*)(smem + SM_XL + off) = make_uint4(lp[0], lp[1], lp[2], lp[3]);
        }
    }
    __syncthreads();

    // ---- Fragment addressing (verified mapping, R5/R8/R9); warp owns 16x128
    const uint32_t lsw = (uint32_t)((lid & 7) << 4);

    const int a_m = (((lid >> 3) & 1) << 3) + (lid & 7);
    const uint32_t a_kb0 = (uint32_t)((((lid >> 4) & 1) << 3) * 2);
    const uint32_t a_rbase = (uint32_t)((wid * 16 + a_m) * 256);

    const int b_nl = (((lid >> 4) & 1) << 3) + (lid & 7);
    const uint32_t b_kb0 = (uint32_t)((((lid >> 3) & 1) << 3) * 2);
    const uint32_t b_rbase0 = (uint32_t)(b_nl * 256);

    float acc[16][4];
#pragma unroll
    for (int nb = 0; nb < 16; nb++)
#pragma unroll
        for (int i = 0; i < 4; i++) acc[nb][i] = 0.f;

#pragma unroll
    for (int ks = 0; ks < 8; ks++) {
        const uint32_t akb = (a_kb0 + (uint32_t)(ks * 32)) ^ lsw;
        const uint32_t bkb = (b_kb0 + (uint32_t)(ks * 32)) ^ lsw;
        uint32_t ah0, ah1, ah2, ah3, al0, al1, al2, al3;
        LDSM_X4(ah0, ah1, ah2, ah3, sb + SM_XH + a_rbase + akb);
        LDSM_X4(al0, al1, al2, al3, sb + SM_XL + a_rbase + akb);
#pragma unroll
        for (int p = 0; p < 8; p++) {
            const uint32_t brow = b_rbase0 + (uint32_t)(p * 16 * 256);
            uint32_t b0, b1, b2, b3;
            LDSM_X4(b0, b1, b2, b3, sb + SM_WH + brow + bkb);
            float* c0 = acc[2 * p];
            float* c1 = acc[2 * p + 1];
            MMA_BF16(c0[0], c0[1], c0[2], c0[3], ah0, ah1, ah2, ah3, b0, b1);
            MMA_BF16(c1[0], c1[1], c1[2], c1[3], ah0, ah1, ah2, ah3, b2, b3);
            MMA_BF16(c0[0], c0[1], c0[2], c0[3], al0, al1, al2, al3, b0, b1);
            MMA_BF16(c1[0], c1[1], c1[2], c1[3], al0, al1, al2, al3, b2, b3);
        }
    }

    // ---- Epilogue: write bf16 xt. (c0,c1)=row g cols 2q..+1 ; (c2,c3)=row g+8
    const int g = lid >> 2;
    const int q = lid & 3;
    const int m0 = row0 + wid * 16 + g;
    const int m1 = m0 + 8;
#pragma unroll
    for (int nb = 0; nb < 16; nb++) {
        int col = nb * 8 + q * 2;
        __nv_bfloat16 p00 = __float2bfloat16(acc[nb][0]);
        __nv_bfloat16 p01 = __float2bfloat16(acc[nb][1]);
        __nv_bfloat16 p10 = __float2bfloat16(acc[nb][2]);
        __nv_bfloat16 p11 = __float2bfloat16(acc[nb][3]);
        uint32_t w0 = (uint32_t)*(uint16_t*)&p00 | ((uint32_t)*(uint16_t*)&p01 << 16);
        uint32_t w1 = (uint32_t)*(uint16_t*)&p10 | ((uint32_t)*(uint16_t*)&p11 << 16);
        if (m0 < M) *(uint32_t*)(Xtb + (size_t)m0 * EMBED + col) = w0;
        if (m1 < M) *(uint32_t*)(Xtb + (size_t)m1 * EMBED + col) = w1;
    }
}

// ---------------------------------------------------------------------------
// SpMM + residual, bf16 gather, edge-paired:
//   out[r] = x[r] + sum vals[e] * bf16(xt)[cols[e]]
// One warp per row. Each iteration handles TWO edges: lanes 0-15 gather edge j,
// lanes 16-31 edge j+1 (LDG.128 = 8 bf16 cols per lane). Halves combined once
// per row via shfl. Shfl count and LDG instruction count halve per edge.
// ---------------------------------------------------------------------------
__global__ __launch_bounds__(256) void spmm_kernel(const float* __restrict__ x,
                                                   const int* __restrict__ cols,
                                                   const float* __restrict__ vals,
                                                   float* __restrict__ out,
                                                   float* __restrict__ out0,
                                                   int M) {
    int warp = (blockIdx.x * blockDim.x + threadIdx.x) >> 5;
    int lane = threadIdx.x & 31;
    if (warp >= M) return;
    const int r = warp;
    const int s = g_row_ptr[r];
    const int e = g_row_ptr[r + 1];
    const int half = lane >> 4;      // 0: even edges, 1: odd edges
    const int lc = lane & 15;        // owns cols lc*8 .. lc*8+7

    float acc[8];
#pragma unroll
    for (int i = 0; i < 8; i++) acc[i] = 0.f;

    for (int base = s; base < e; base += 32) {
        int idx = base + lane;
        int   c = 0;                 // default row 0: safe address for idle lanes
        float v = 0.f;
        if (idx < e) { c = __ldg(cols + idx); v = __ldg(vals + idx); }
        int cnt = min(32, e - base);
        for (int j = 0; j < cnt; j += 2) {
            int src = j + half;
            int   cj = __shfl_sync(0xffffffffu, c, src & 31);
            float vj = __shfl_sync(0xffffffffu, v, src & 31);
            if (src >= cnt) vj = 0.f;
            uint4 raw = *(const uint4*)(g_xtb + (size_t)cj * EMBED + lc * 8);
            acc[0] += vj * bf_lo(raw.x);
            acc[1] += vj * bf_hi(raw.x);
            acc[2] += vj * bf_lo(raw.y);
            acc[3] += vj * bf_hi(raw.y);
            acc[4] += vj * bf_lo(raw.z);
            acc[5] += vj * bf_hi(raw.z);
            acc[6] += vj * bf_lo(raw.w);
            acc[7] += vj * bf_hi(raw.w);
        }
    }

    // combine odd-edge partials (lanes 16-31) into lanes 0-15
#pragma unroll
    for (int i = 0; i < 8; i++)
        acc[i] += __shfl_down_sync(0xffffffffu, acc[i], 16);

    if (half == 0) {
        const float4* xp = (const float4*)(x + (size_t)r * EMBED + lc * 8);
        float4 xv0 = xp[0];
        float4 xv1 = xp[1];
        if (out0) {
            float4* o0 = (float4*)(out0 + (size_t)r * EMBED + lc * 8);
            o0[0] = xv0;
            o0[1] = xv1;
        }
        float4* op = (float4*)(out + (size_t)r * EMBED + lc * 8);
        op[0] = make_float4(acc[0] + xv0.x, acc[1] + xv0.y, acc[2] + xv0.z, acc[3] + xv0.w);
        op[1] = make_float4(acc[4] + xv1.x, acc[5] + xv1.y, acc[6] + xv1.z, acc[7] + xv1.w);
    }
}

// ---------------------------------------------------------------------------
// kernel_launch
// ---------------------------------------------------------------------------
extern "C" void kernel_launch(void* const* d_in, const int* in_sizes, int n_in,
                              void* d_out, int out_size) {
    const float* ue   = (const float*)d_in[0];
    const int*   rows = (const int*)  d_in[1];
    const int*   cols = (const int*)  d_in[2];
    const float* vals = (const float*)d_in[3];
    const float* W0   = (const float*)d_in[4];
    const float* W1   = (const float*)d_in[5];
    float* out = (float*)d_out;

    const int M = in_sizes[0] / EMBED;
    const int E = in_sizes[1];
    const size_t layer_elems = (size_t)M * EMBED;

    uint16_t* xtb_ptr;
    cudaGetSymbolAddress((void**)&xtb_ptr, g_xtb);

    cudaFuncSetAttribute(gemm_2p_kernel, cudaFuncAttributeMaxDynamicSharedMemorySize, SM_TOTAL);

    prep_w_kernel<<<128, 256>>>(W0, W1);
    build_rowptr_kernel<<<(E + 255) / 256, 256>>>(rows, E, M);

    const int gemm_blocks = (M + TILE_M - 1) / TILE_M;
    const int spmm_blocks = (M * 32 + 255) / 256;

    // Layer 1 (SpMM also emits out[0] = user_embeds)
    gemm_2p_kernel<<<gemm_blocks, 256, SM_TOTAL>>>(ue, 0, xtb_ptr, M);
    spmm_kernel<<<spmm_blocks, 256>>>(ue, cols, vals, out + layer_elems, out, M);

    // Layer 2
    gemm_2p_kernel<<<gemm_blocks, 256, SM_TOTAL>>>(out + layer_elems, 1, xtb_ptr, M);
    spmm_kernel<<<spmm_blocks, 256>>>(out + layer_elems, cols, vals,
                                      out + 2 * layer_elems, nullptr, M);
}

// round 11
// speedup vs baseline: 1.5532x; 1.0482x over previous
#include <cuda_runtime.h>
#include <cuda_bf16.h>
#include <stdint.h>

#define MAX_USERS 100000
#define EMBED 128
#define TILE_M 128           // rows per GEMM CTA

// ---------------------------------------------------------------------------
// Scratch in __device__ globals (no allocation allowed anywhere)
// ---------------------------------------------------------------------------
__device__ uint16_t g_xtb[(size_t)MAX_USERS * EMBED]; // x @ W result, bf16
__device__ int      g_row_ptr[MAX_USERS + 1];
__device__ uint16_t g_wt[2][EMBED * EMBED];           // [layer] W^T bf16, [n][k]

// ---------------------------------------------------------------------------
// SMEM: xh (128x256B) | w (128x256B) = 64KB.
// Swizzle: addr = row*256 + (kb ^ ((row&7)<<4)) (layout verified R5/R8/R9/R10).
// ---------------------------------------------------------------------------
#define SM_XH 0
#define SM_WH 32768
#define SM_TOTAL 65536

__device__ __forceinline__ uint32_t smem_u32(const void* p) {
    uint32_t a;
    asm("{ .reg .u64 t; cvta.to.shared.u64 t, %1; cvt.u32.u64 %0, t; }" : "=r"(a) : "l"(p));
    return a;
}

#define LDSM_X4(f0, f1, f2, f3, addr) \
    asm volatile("ldmatrix.sync.aligned.m8n8.x4.shared.b16 {%0,%1,%2,%3}, [%4];" \
        : "=r"(f0), "=r"(f1), "=r"(f2), "=r"(f3) : "r"(addr))

#define MMA_BF16(c0, c1, c2, c3, a0, a1, a2, a3, b0, b1) \
    asm volatile("mma.sync.aligned.m16n8k16.row.col.f32.bf16.bf16.f32 " \
        "{%0,%1,%2,%3}, {%4,%5,%6,%7}, {%8,%9}, {%0,%1,%2,%3};" \
        : "+f"(c0), "+f"(c1), "+f"(c2), "+f"(c3) \
        : "r"(a0), "r"(a1), "r"(a2), "r"(a3), "r"(b0), "r"(b1))

// ---------------------------------------------------------------------------
// Prep: W (row-major [k][n]) -> W^T bf16 in [n][k] order
// ---------------------------------------------------------------------------
__global__ void prep_w_kernel(const float* __restrict__ W0, const float* __restrict__ W1) {
    int layer = blockIdx.x >> 6;
    int idx = (blockIdx.x & 63) * 256 + threadIdx.x;   // 0..16383
    const float* W = layer ? W1 : W0;
    int k = idx >> 7, n = idx & 127;
    __nv_bfloat16 h = __float2bfloat16(W[idx]);
    g_wt[layer][n * EMBED + k] = *(uint16_t*)&h;
}

// ---------------------------------------------------------------------------
// Build CSR row_ptr from sorted s_rows
// ---------------------------------------------------------------------------
__global__ void build_rowptr_kernel(const int* __restrict__ rows, int E, int M) {
    int e = blockIdx.x * blockDim.x + threadIdx.x;
    if (e >= E) return;
    int r = rows[e];
    if (e == 0) { for (int i = 0; i <= r; i++) g_row_ptr[i] = 0; }
    else { int rp = rows[e - 1]; for (int i = rp + 1; i <= r; i++) g_row_ptr[i] = e; }
    if (e == E - 1) { for (int i = r + 1; i <= M; i++) g_row_ptr[i] = E; }
}

// ---------------------------------------------------------------------------
// 1-product bf16 HMMA GEMM: Xtb(bf16) = A[M,128] @ W[128,128]
// (A-rounding measured to contribute nothing vs W-rounding: R8 vs R9/R10.)
// CTA: 256 threads / 8 warps; TILE_M=128; warp w: rows w*16..+15, all 128 cols.
// ---------------------------------------------------------------------------
__global__ __launch_bounds__(256, 2) void gemm_1p_kernel(const float* __restrict__ A,
                                                         int layer,
                                                         uint16_t* __restrict__ Xtb,
                                                         int M) {
    extern __shared__ char smem[];
    const uint32_t sb = smem_u32(smem);
    const int tid = threadIdx.x;
    const int wid = tid >> 5;
    const int lid = tid & 31;
    const int row0 = blockIdx.x * TILE_M;

    // ---- Stage W^T bf16 (swizzled): thread t -> n = t>>1, 128B half h = t&1
    {
        const uint4* gh = (const uint4*)g_wt[layer];
        int n = tid >> 1, h = tid & 1;
        uint32_t nsw = (uint32_t)((n & 7) << 4);
        uint32_t rbase = (uint32_t)(n * 256);
#pragma unroll
        for (int c = 0; c < 8; c++) {
            uint32_t kb = (uint32_t)(h * 128 + c * 16);
            *(uint4*)(smem + SM_WH + rbase + (kb ^ nsw)) = gh[n * 16 + h * 8 + c];
        }
    }

    // ---- Stage A rows -> bf16 (swizzled): thread t -> row t&127, half t>>7
    // Rows beyond M clamp to M-1 (their outputs are never read or written).
    {
        int r = tid & 127, h = tid >> 7;
        int grow = row0 + r;
        if (grow >= M) grow = M - 1;
        const float4* src = (const float4*)(A + (size_t)grow * EMBED + h * 64);
        uint32_t rsw = (uint32_t)((r & 7) << 4);
        uint32_t rbase = (uint32_t)(r * 256);
#pragma unroll
        for (int c = 0; c < 8; c++) {            // 8 x 16B chunks (8 bf16 each)
            uint32_t hp[4];
#pragma unroll
            for (int i = 0; i < 2; i++) {
                float4 f = src[c * 2 + i];
                __nv_bfloat16 h0 = __float2bfloat16(f.x), h1 = __float2bfloat16(f.y);
                __nv_bfloat16 h2 = __float2bfloat16(f.z), h3 = __float2bfloat16(f.w);
                hp[2 * i]     = (uint32_t)*(uint16_t*)&h0 | ((uint32_t)*(uint16_t*)&h1 << 16);
                hp[2 * i + 1] = (uint32_t)*(uint16_t*)&h2 | ((uint32_t)*(uint16_t*)&h3 << 16);
            }
            uint32_t kb = (uint32_t)(h * 128 + c * 16);
            *(uint4*)(smem + SM_XH + rbase + (kb ^ rsw)) = make_uint4(hp[0], hp[1], hp[2], hp[3]);
        }
    }
    __syncthreads();

    // ---- Fragment addressing (verified mapping); warp owns rows wid*16..+15
    const uint32_t lsw = (uint32_t)((lid & 7) << 4);

    const int a_m = (((lid >> 3) & 1) << 3) + (lid & 7);
    const uint32_t a_kb0 = (uint32_t)((((lid >> 4) & 1) << 3) * 2);
    const uint32_t a_rbase = (uint32_t)((wid * 16 + a_m) * 256);

    const int b_nl = (((lid >> 4) & 1) << 3) + (lid & 7);
    const uint32_t b_kb0 = (uint32_t)((((lid >> 3) & 1) << 3) * 2);
    const uint32_t b_rbase0 = (uint32_t)(b_nl * 256);

    float acc[16][4];
#pragma unroll
    for (int nb = 0; nb < 16; nb++)
#pragma unroll
        for (int i = 0; i < 4; i++) acc[nb][i] = 0.f;

#pragma unroll
    for (int ks = 0; ks < 8; ks++) {
        const uint32_t akb = (a_kb0 + (uint32_t)(ks * 32)) ^ lsw;
        const uint32_t bkb = (b_kb0 + (uint32_t)(ks * 32)) ^ lsw;
        uint32_t a0, a1, a2, a3;
        LDSM_X4(a0, a1, a2, a3, sb + SM_XH + a_rbase + akb);
#pragma unroll
        for (int p = 0; p < 8; p++) {
            const uint32_t brow = b_rbase0 + (uint32_t)(p * 16 * 256);
            uint32_t b0, b1, b2, b3;
            LDSM_X4(b0, b1, b2, b3, sb + SM_WH + brow + bkb);
            MMA_BF16(acc[2 * p][0], acc[2 * p][1], acc[2 * p][2], acc[2 * p][3],
                     a0, a1, a2, a3, b0, b1);
            MMA_BF16(acc[2 * p + 1][0], acc[2 * p + 1][1], acc[2 * p + 1][2], acc[2 * p + 1][3],
                     a0, a1, a2, a3, b2, b3);
        }
    }

    // ---- Epilogue: write bf16 xt. (c0,c1)=row g cols 2q..+1 ; (c2,c3)=row g+8
    const int g = lid >> 2;
    const int q = lid & 3;
    const int m0 = row0 + wid * 16 + g;
    const int m1 = m0 + 8;
#pragma unroll
    for (int nb = 0; nb < 16; nb++) {
        int col = nb * 8 + q * 2;
        __nv_bfloat16 p00 = __float2bfloat16(acc[nb][0]);
        __nv_bfloat16 p01 = __float2bfloat16(acc[nb][1]);
        __nv_bfloat16 p10 = __float2bfloat16(acc[nb][2]);
        __nv_bfloat16 p11 = __float2bfloat16(acc[nb][3]);
        uint32_t w0 = (uint32_t)*(uint16_t*)&p00 | ((uint32_t)*(uint16_t*)&p01 << 16);
        uint32_t w1 = (uint32_t)*(uint16_t*)&p10 | ((uint32_t)*(uint16_t*)&p11 << 16);
        if (m0 < M) *(uint32_t*)(Xtb + (size_t)m0 * EMBED + col) = w0;
        if (m1 < M) *(uint32_t*)(Xtb + (size_t)m1 * EMBED + col) = w1;
    }
}

// ---------------------------------------------------------------------------
// SpMM + residual, bf16 gather — exact R9 structure (62.4us, best measured):
//   out[r] = x[r] + sum vals[e] * bf16(xt)[cols[e]]
// One warp per row; lane owns 4 cols (uint2 = 4 bf16 = 8 B gather per lane).
// ---------------------------------------------------------------------------
__global__ __launch_bounds__(256) void spmm_kernel(const float* __restrict__ x,
                                                   const int* __restrict__ cols,
                                                   const float* __restrict__ vals,
                                                   float* __restrict__ out,
                                                   float* __restrict__ out0,
                                                   int M) {
    int warp = (blockIdx.x * blockDim.x + threadIdx.x) >> 5;
    int lane = threadIdx.x & 31;
    if (warp >= M) return;
    int r = warp;
    int s = g_row_ptr[r];
    int e = g_row_ptr[r + 1];

    float4 acc = make_float4(0.f, 0.f, 0.f, 0.f);
    for (int base = s; base < e; base += 32) {
        int idx = base + lane;
        int   c = 0;
        float v = 0.f;
        if (idx < e) { c = __ldg(cols + idx); v = __ldg(vals + idx); }
        int cnt = min(32, e - base);
        for (int j = 0; j < cnt; j++) {
            int   cj = __shfl_sync(0xffffffffu, c, j);
            float vj = __shfl_sync(0xffffffffu, v, j);
            uint2 raw = ((const uint2*)(g_xtb + (size_t)cj * EMBED))[lane];
            float f0 = __uint_as_float(raw.x << 16);
            float f1 = __uint_as_float(raw.x & 0xffff0000u);
            float f2 = __uint_as_float(raw.y << 16);
            float f3 = __uint_as_float(raw.y & 0xffff0000u);
            acc.x += vj * f0;
            acc.y += vj * f1;
            acc.z += vj * f2;
            acc.w += vj * f3;
        }
    }
    float4 xv = ((const float4*)(x + (size_t)r * EMBED))[lane];
    if (out0) ((float4*)(out0 + (size_t)r * EMBED))[lane] = xv;
    acc.x += xv.x; acc.y += xv.y; acc.z += xv.z; acc.w += xv.w;
    ((float4*)(out + (size_t)r * EMBED))[lane] = acc;
}

// ---------------------------------------------------------------------------
// kernel_launch
// ---------------------------------------------------------------------------
extern "C" void kernel_launch(void* const* d_in, const int* in_sizes, int n_in,
                              void* d_out, int out_size) {
    const float* ue   = (const float*)d_in[0];
    const int*   rows = (const int*)  d_in[1];
    const int*   cols = (const int*)  d_in[2];
    const float* vals = (const float*)d_in[3];
    const float* W0   = (const float*)d_in[4];
    const float* W1   = (const float*)d_in[5];
    float* out = (float*)d_out;

    const int M = in_sizes[0] / EMBED;
    const int E = in_sizes[1];
    const size_t layer_elems = (size_t)M * EMBED;

    uint16_t* xtb_ptr;
    cudaGetSymbolAddress((void**)&xtb_ptr, g_xtb);

    cudaFuncSetAttribute(gemm_1p_kernel, cudaFuncAttributeMaxDynamicSharedMemorySize, SM_TOTAL);

    prep_w_kernel<<<128, 256>>>(W0, W1);
    build_rowptr_kernel<<<(E + 255) / 256, 256>>>(rows, E, M);

    const int gemm_blocks = (M + TILE_M - 1) / TILE_M;
    const int spmm_blocks = (M * 32 + 255) / 256;

    // Layer 1 (SpMM also emits out[0] = user_embeds)
    gemm_1p_kernel<<<gemm_blocks, 256, SM_TOTAL>>>(ue, 0, xtb_ptr, M);
    spmm_kernel<<<spmm_blocks, 256>>>(ue, cols, vals, out + layer_elems, out, M);

    // Layer 2
    gemm_1p_kernel<<<gemm_blocks, 256, SM_TOTAL>>>(out + layer_elems, 1, xtb_ptr, M);
    spmm_kernel<<<spmm_blocks, 256>>>(out + layer_elems, cols, vals,
                                      out + 2 * layer_elems, nullptr, M);
}